// round 9
// baseline (speedup 1.0000x reference)
#include <cuda_runtime.h>
#include <cuda_bf16.h>
#include <math.h>
#include <stdint.h>

// ---------------- problem constants ----------------
#define BTOK   32768
#define DIMSZ  1024
#define NEXP   8
#define TOPK   2
#define HID    4096
#define CAPCT  10240            // ceil(1.25 * 32768 * 2 / 8)
#define NSLOT  (BTOK * TOPK)    // 65536

// ---------------- GEMM tiling ----------------
#define BM 128
#define BN 128
#define BK 32                   // K elements per chunk
#define ROWB 80                 // padded row stride bytes
// stage regions: A bf16-hi rows (64B data), A fp8 rows (hi8 0-31, lo8 32-63), B likewise
#define RG_AH 0
#define RG_A8 10240
#define RG_BH 20480
#define RG_B8 30720
#define STG_BYTES 40960
#define NSTAGE 3
#define SMEM_G (NSTAGE * STG_BYTES)   // 122880, dynamic (opt-in)

// fp8 pre-scales (powers of two; both correction products carry 2^13)
#define S_AH8 4.0f      // x, h "hi" fp8
#define S_AL8 128.0f    // x, h "lo" fp8
#define S_WH8 64.0f     // w "hi" fp8
#define S_WL8 2048.0f   // w "lo" fp8
#define INV_CORR (1.0f / 8192.0f)

// ---------------- device scratch (static, no allocs) ----------------
__device__ __align__(128) __nv_bfloat16 g_x_hi[(size_t)BTOK * DIMSZ];
__device__ __align__(128) uint8_t       g_x_hi8[(size_t)BTOK * DIMSZ];
__device__ __align__(128) uint8_t       g_x_lo8[(size_t)BTOK * DIMSZ];
__device__ __align__(128) __nv_bfloat16 g_w1t_hi[(size_t)NEXP * HID * DIMSZ]; // [e][n=hid][k=dim]
__device__ __align__(128) uint8_t       g_w1t_hi8[(size_t)NEXP * HID * DIMSZ];
__device__ __align__(128) uint8_t       g_w1t_lo8[(size_t)NEXP * HID * DIMSZ];
__device__ __align__(128) __nv_bfloat16 g_w2t_hi[(size_t)NEXP * DIMSZ * HID]; // [e][n=dim][k=hid]
__device__ __align__(128) uint8_t       g_w2t_hi8[(size_t)NEXP * DIMSZ * HID];
__device__ __align__(128) uint8_t       g_w2t_lo8[(size_t)NEXP * DIMSZ * HID];
__device__ __align__(128) __nv_bfloat16 g_h_hi[(size_t)NEXP * CAPCT * HID];
__device__ __align__(128) uint8_t       g_h_hi8[(size_t)NEXP * CAPCT * HID];
__device__ __align__(128) uint8_t       g_h_lo8[(size_t)NEXP * CAPCT * HID];
__device__ __align__(128) int                g_tok[NEXP * CAPCT];
__device__ __align__(128) float              g_gw[NEXP * CAPCT];
__device__ __align__(128) int                g_topi[NSLOT];
__device__ __align__(128) float              g_topw[NSLOT];
__device__ int                g_count[NEXP];
__device__ int                g_len[NEXP];
__device__ float              g_usage[NEXP];
__device__ float              g_z2;
__device__ unsigned long long g_thr[NEXP];

// ---------------- helpers ----------------
__device__ __forceinline__ uint32_t smem_u32(const void* p) {
    uint32_t a;
    asm("{ .reg .u64 t; cvta.to.shared.u64 t, %1; cvt.u32.u64 %0, t; }" : "=r"(a) : "l"(p));
    return a;
}
__device__ __forceinline__ void cp16(uint32_t d, const void* s) {
    asm volatile("cp.async.cg.shared.global [%0], [%1], 16;" :: "r"(d), "l"(s));
}
__device__ __forceinline__ void cp_commit() { asm volatile("cp.async.commit_group;"); }
__device__ __forceinline__ void cp_wait1()  { asm volatile("cp.async.wait_group 1;"); }

__device__ __forceinline__ void ldsm4(uint32_t* r, uint32_t a) {
    asm volatile("ldmatrix.sync.aligned.m8n8.x4.shared.b16 {%0,%1,%2,%3}, [%4];"
                 : "=r"(r[0]), "=r"(r[1]), "=r"(r[2]), "=r"(r[3]) : "r"(a));
}
__device__ __forceinline__ void mma16816(float* d, const uint32_t* a, uint32_t b0, uint32_t b1) {
    asm volatile("mma.sync.aligned.m16n8k16.row.col.f32.bf16.bf16.f32 "
                 "{%0,%1,%2,%3}, {%4,%5,%6,%7}, {%8,%9}, {%0,%1,%2,%3};"
                 : "+f"(d[0]), "+f"(d[1]), "+f"(d[2]), "+f"(d[3])
                 : "r"(a[0]), "r"(a[1]), "r"(a[2]), "r"(a[3]), "r"(b0), "r"(b1));
}
__device__ __forceinline__ void mma_fp8(float* d, const uint32_t* a, uint32_t b0, uint32_t b1) {
    asm volatile("mma.sync.aligned.m16n8k32.row.col.f32.e4m3.e4m3.f32 "
                 "{%0,%1,%2,%3}, {%4,%5,%6,%7}, {%8,%9}, {%0,%1,%2,%3};"
                 : "+f"(d[0]), "+f"(d[1]), "+f"(d[2]), "+f"(d[3])
                 : "r"(a[0]), "r"(a[1]), "r"(a[2]), "r"(a[3]), "r"(b0), "r"(b1));
}
// pack two floats to e4m3x2: byte0 = lo_elem, byte1 = hi_elem
__device__ __forceinline__ uint16_t cvt_fp8x2(float hi_elem, float lo_elem) {
    uint16_t r;
    asm("cvt.rn.satfinite.e4m3x2.f32 %0, %1, %2;" : "=h"(r) : "f"(hi_elem), "f"(lo_elem));
    return r;
}
__device__ __forceinline__ uint8_t cvt_fp8(float v) {
    return (uint8_t)(cvt_fp8x2(0.f, v) & 0xFF);
}

__device__ __forceinline__ unsigned long long make_key(float w, int slot) {
    return ((unsigned long long)__float_as_uint(w) << 32) |
           (unsigned long long)(0xFFFFFFFFu - (unsigned)slot);
}
__device__ __forceinline__ float gelu_exact(float v) {
    return 0.5f * v * (1.0f + erff(v * 0.70710678118654752f));
}
__device__ __forceinline__ uint32_t pack_bf2(float a, float b) {
    __nv_bfloat16 h0 = __float2bfloat16(a), h1 = __float2bfloat16(b);
    return (uint32_t)__bfloat16_as_ushort(h0) | ((uint32_t)__bfloat16_as_ushort(h1) << 16);
}

// ---------------- init ----------------
__global__ void init_kernel() {
    int t = threadIdx.x;
    if (t < NEXP) { g_count[t] = 0; g_len[t] = 0; g_usage[t] = 0.f; }
    if (t == 0)   { g_z2 = 0.f; }
}

// ---------------- conversions ----------------
__global__ __launch_bounds__(256) void conv_x_kernel(const float* __restrict__ x) {
    size_t i = (size_t)blockIdx.x * 256 + threadIdx.x;        // float4 index
    float4 v = ((const float4*)x)[i];
    float f[4] = {v.x, v.y, v.z, v.w};
    uint32_t ph[2];
    float l[4];
#pragma unroll
    for (int q = 0; q < 2; q++) {
        float a = f[2 * q], b = f[2 * q + 1];
        __nv_bfloat16 h0 = __float2bfloat16(a), h1 = __float2bfloat16(b);
        ph[q] = (uint32_t)__bfloat16_as_ushort(h0) | ((uint32_t)__bfloat16_as_ushort(h1) << 16);
        l[2 * q]     = a - __bfloat162float(h0);
        l[2 * q + 1] = b - __bfloat162float(h1);
    }
    ((uint2*)g_x_hi)[i] = make_uint2(ph[0], ph[1]);
    uint32_t hi8 = (uint32_t)cvt_fp8x2(f[1] * S_AH8, f[0] * S_AH8) |
                   ((uint32_t)cvt_fp8x2(f[3] * S_AH8, f[2] * S_AH8) << 16);
    uint32_t lo8 = (uint32_t)cvt_fp8x2(l[1] * S_AL8, l[0] * S_AL8) |
                   ((uint32_t)cvt_fp8x2(l[3] * S_AL8, l[2] * S_AL8) << 16);
    ((uint32_t*)g_x_hi8)[i] = hi8;
    ((uint32_t*)g_x_lo8)[i] = lo8;
}

// transpose + split: src [e][K_][N_] fp32 -> dst [e][N_][K_] bf16-hi + fp8 hi/lo
// Destination globals bound INSIDE device code (host-passed __device__ symbols
// resolve to the host shadow -> silent ATS writes on GB300).
__global__ __launch_bounds__(256) void conv_tr_kernel(const float* __restrict__ src,
                                                      int which, int K_, int N_) {
    __nv_bfloat16* dhi = which ? g_w2t_hi  : g_w1t_hi;
    uint8_t*       d8h = which ? g_w2t_hi8 : g_w1t_hi8;
    uint8_t*       d8l = which ? g_w2t_lo8 : g_w1t_lo8;
    __shared__ float t[32][33];
    int e = blockIdx.z;
    size_t ebase = (size_t)e * K_ * N_;
    src += ebase; dhi += ebase; d8h += ebase; d8l += ebase;
    int n0 = blockIdx.x * 32, k0 = blockIdx.y * 32;
    int tx = threadIdx.x & 31, ty = threadIdx.x >> 5;
#pragma unroll
    for (int i = 0; i < 32; i += 8)
        t[ty + i][tx] = src[(size_t)(k0 + ty + i) * N_ + n0 + tx];
    __syncthreads();
#pragma unroll
    for (int i = 0; i < 32; i += 8) {
        float v = t[tx][ty + i];
        __nv_bfloat16 h = __float2bfloat16(v);
        float l = v - __bfloat162float(h);
        size_t o = (size_t)(n0 + ty + i) * K_ + k0 + tx;
        dhi[o] = h;
        d8h[o] = cvt_fp8(v * S_WH8);
        d8l[o] = cvt_fp8(l * S_WL8);
    }
}

// ---------------- router ----------------
__global__ __launch_bounds__(256) void router_kernel(const float* __restrict__ x,
                                                     const float* __restrict__ rw) {
    __shared__ float sW[NEXP * DIMSZ];
    __shared__ float s_usage[NEXP];
    __shared__ int   s_count[NEXP];
    __shared__ float s_z2;

    int tid = threadIdx.x;
    for (int i = tid; i < NEXP * DIMSZ; i += 256) sW[i] = rw[i];
    if (tid < NEXP) { s_usage[tid] = 0.f; s_count[tid] = 0; }
    if (tid == 0) s_z2 = 0.f;
    __syncthreads();

    int warp = tid >> 5, lane = tid & 31;
    for (int t = 0; t < 4; t++) {
        int row = blockIdx.x * 32 + warp * 4 + t;
        const float* xr = x + (size_t)row * DIMSZ;
        float acc[NEXP];
#pragma unroll
        for (int e = 0; e < NEXP; e++) acc[e] = 0.f;
        for (int i = lane; i < DIMSZ; i += 32) {
            float xv = xr[i];
#pragma unroll
            for (int e = 0; e < NEXP; e++) acc[e] = fmaf(xv, sW[e * DIMSZ + i], acc[e]);
        }
#pragma unroll
        for (int e = 0; e < NEXP; e++)
#pragma unroll
            for (int off = 16; off; off >>= 1)
                acc[e] += __shfl_xor_sync(0xFFFFFFFFu, acc[e], off);

        if (lane == 0) {
            float m = acc[0];
#pragma unroll
            for (int e = 1; e < NEXP; e++) m = fmaxf(m, acc[e]);
            float p[NEXP]; float se = 0.f;
#pragma unroll
            for (int e = 0; e < NEXP; e++) { p[e] = expf(acc[e] - m); se += p[e]; }
            float inv = 1.f / se;
#pragma unroll
            for (int e = 0; e < NEXP; e++) p[e] *= inv;
            float z = m + logf(se);

            int i0 = 0;
#pragma unroll
            for (int e = 1; e < NEXP; e++) if (acc[e] > acc[i0]) i0 = e;
            int i1 = -1;
#pragma unroll
            for (int e = 0; e < NEXP; e++)
                if (e != i0 && (i1 < 0 || acc[e] > acc[i1])) i1 = e;

            float p0 = p[i0], p1 = p[i1];
            float s = fmaxf(p0 + p1, 1e-9f);
            g_topi[row * 2 + 0] = i0; g_topw[row * 2 + 0] = p0 / s;
            g_topi[row * 2 + 1] = i1; g_topw[row * 2 + 1] = p1 / s;

            atomicAdd(&s_count[i0], 1);
            atomicAdd(&s_count[i1], 1);
#pragma unroll
            for (int e = 0; e < NEXP; e++) atomicAdd(&s_usage[e], p[e]);
            atomicAdd(&s_z2, z * z);
        }
    }
    __syncthreads();
    if (tid < NEXP) {
        atomicAdd(&g_usage[tid], s_usage[tid]);
        atomicAdd(&g_count[tid], s_count[tid]);
    }
    if (tid == 0) atomicAdd(&g_z2, s_z2);
}

// ---------------- exact capacity threshold (radix select, only on overflow) ----------------
__global__ void select_kernel() {
    int e = blockIdx.x;
    if (g_count[e] <= CAPCT) {
        if (threadIdx.x == 0) g_thr[e] = 0ULL;
        return;
    }
    __shared__ unsigned int       hist[256];
    __shared__ unsigned long long s_prefix;
    __shared__ int                s_rem;
    if (threadIdx.x == 0) { s_prefix = 0ULL; s_rem = CAPCT; }

    for (int pass = 7; pass >= 0; pass--) {
        __syncthreads();
        for (int i = threadIdx.x; i < 256; i += blockDim.x) hist[i] = 0u;
        __syncthreads();
        unsigned long long prefix = s_prefix;
        for (int s = threadIdx.x; s < NSLOT; s += blockDim.x) {
            if (g_topi[s] == e) {
                unsigned long long key = make_key(g_topw[s], s);
                bool match = (pass == 7) || ((key >> ((pass + 1) * 8)) == prefix);
                if (match)
                    atomicAdd(&hist[(unsigned)((key >> (pass * 8)) & 255ULL)], 1u);
            }
        }
        __syncthreads();
        if (threadIdx.x == 0) {
            int rem = s_rem;
            int digit = 0;
            for (int b = 255; b >= 0; b--) {
                if ((int)hist[b] >= rem) { digit = b; break; }
                rem -= (int)hist[b];
            }
            s_prefix = (s_prefix << 8) | (unsigned long long)digit;
            s_rem = rem;
        }
    }
    __syncthreads();
    if (threadIdx.x == 0) g_thr[e] = s_prefix;
}

// ---------------- build per-expert token lists ----------------
__global__ void build_kernel() {
    int s = blockIdx.x * blockDim.x + threadIdx.x;
    if (s >= NSLOT) return;
    int e = g_topi[s];
    float w = g_topw[s];
    bool keep = (g_count[e] <= CAPCT) || (make_key(w, s) >= g_thr[e]);
    if (keep) {
        int pos = atomicAdd(&g_len[e], 1);
        g_tok[e * CAPCT + pos] = s >> 1;
        g_gw[e * CAPCT + pos]  = w;
    }
}

// ======================================================================
// GEMM core: main term in bf16 HMMA (m16n8k16), corrections in fp8 QMMA
// (m16n8k32, e4m3): acc = Ahi*Bhi + [Alo8*Bhi8 + Ahi8*Blo8] * 2^-13.
// 128x128 CTA tile, K-chunk 32, 3-stage cp.async pipeline.
// 8 warps: (wm,wn), wm in {0,1} x 64 rows, wn in {0..3} x 32 cols.
// ======================================================================
template <bool IS_G1>
__device__ __forceinline__ void gemm_core(int e, int len, int row0, int col0, uint32_t sb,
                                          float accm[4][4][4], float accc[4][4][4]) {
    int tid = threadIdx.x, lane = tid & 31, wid = tid >> 5;
    int wm = wid & 1, wn = wid >> 1;

    // load mapping: row = tid>>1 (0..127), sel = tid&1
    int lrow = tid >> 1, lsel = tid & 1;
    const __nv_bfloat16 *aph, *bph;
    const uint8_t *a8, *b8;
    int KTOT;
    if (IS_G1) {
        int gr = row0 + lrow;
        int tok = (gr < len) ? g_tok[e * CAPCT + gr] : 0;
        size_t aoff = (size_t)tok * DIMSZ;
        size_t boff = ((size_t)e * HID + col0 + lrow) * DIMSZ;
        aph = g_x_hi + aoff + lsel * 16;
        a8  = (lsel ? g_x_lo8 : g_x_hi8) + aoff;
        bph = g_w1t_hi + boff + lsel * 16;
        b8  = (lsel ? g_w1t_lo8 : g_w1t_hi8) + boff;
        KTOT = DIMSZ;
    } else {
        size_t aoff = ((size_t)e * CAPCT + row0 + lrow) * HID;
        size_t boff = ((size_t)e * DIMSZ + col0 + lrow) * HID;
        aph = g_h_hi + aoff + lsel * 16;
        a8  = (lsel ? g_h_lo8 : g_h_hi8) + aoff;
        bph = g_w2t_hi + boff + lsel * 16;
        b8  = (lsel ? g_w2t_lo8 : g_w2t_hi8) + boff;
        KTOT = HID;
    }
    const int NK = KTOT / BK;
    uint32_t sA  = sb + RG_AH + lrow * ROWB + lsel * 32;
    uint32_t sA8 = sb + RG_A8 + lrow * ROWB + lsel * 32;
    uint32_t sB  = sb + RG_BH + lrow * ROWB + lsel * 32;
    uint32_t sB8 = sb + RG_B8 + lrow * ROWB + lsel * 32;

    auto load_stage = [&](int st, int kc) {
        uint32_t b = st * STG_BYTES;
        cp16(sA  + b,      aph + kc);
        cp16(sA  + b + 16, aph + kc + 8);
        cp16(sA8 + b,      a8 + kc);
        cp16(sA8 + b + 16, a8 + kc + 16);
        cp16(sB  + b,      bph + kc);
        cp16(sB  + b + 16, bph + kc + 8);
        cp16(sB8 + b,      b8 + kc);
        cp16(sB8 + b + 16, b8 + kc + 16);
    };

    load_stage(0, 0);   cp_commit();
    load_stage(1, BK);  cp_commit();

    // per-lane ldmatrix base offsets (lanes 0-15 rows, 16-31 +16B halves)
    uint32_t arow = (uint32_t)(wm * 64 + (lane & 15)) * ROWB + ((lane >> 4) * 16);
    uint32_t brow = (uint32_t)(wn * 32 + (lane & 15)) * ROWB + ((lane >> 4) * 16);

    for (int c = 0; c < NK; c++) {
        int st = c % NSTAGE;
        cp_wait1();
        __syncthreads();
        if (c + 2 < NK) load_stage((c + 2) % NSTAGE, (c + 2) * BK);
        cp_commit();

        uint32_t sbase = sb + st * STG_BYTES;

        // ---- fp8 corrections: one k32 step covers the whole chunk ----
        {
            uint32_t b8h[2][4], b8l[2][4];
#pragma unroll
            for (int j = 0; j < 2; j++) {
                uint32_t bd = sbase + RG_B8 + brow + j * (16 * ROWB);
                ldsm4(b8h[j], bd);
                ldsm4(b8l[j], bd + 32);
            }
#pragma unroll
            for (int mt = 0; mt < 4; mt++) {
                uint32_t a8h[4], a8l[4];
                uint32_t ad = sbase + RG_A8 + arow + mt * (16 * ROWB);
                ldsm4(a8h, ad);
                ldsm4(a8l, ad + 32);
#pragma unroll
                for (int j = 0; j < 2; j++)
#pragma unroll
                    for (int s = 0; s < 2; s++) {
                        int nt = j * 2 + s;
                        mma_fp8(accc[mt][nt], a8l, b8h[j][s], b8h[j][s + 2]);
                        mma_fp8(accc[mt][nt], a8h, b8l[j][s], b8l[j][s + 2]);
                    }
            }
        }

        // ---- bf16 main: two k16 steps ----
#pragma unroll
        for (int kk = 0; kk < 2; kk++) {
            uint32_t bh[2][4];
#pragma unroll
            for (int j = 0; j < 2; j++)
                ldsm4(bh[j], sbase + RG_BH + brow + j * (16 * ROWB) + kk * 32);
#pragma unroll
            for (int mt = 0; mt < 4; mt++) {
                uint32_t ah[4];
                ldsm4(ah, sbase + RG_AH + arow + mt * (16 * ROWB) + kk * 32);
#pragma unroll
                for (int j = 0; j < 2; j++)
#pragma unroll
                    for (int s = 0; s < 2; s++)
                        mma16816(accm[mt][j * 2 + s], ah, bh[j][s], bh[j][s + 2]);
            }
        }
    }
    __syncthreads();
}

// ---------------- GEMM1: h = gelu(gather(x) @ W1 + b1) ----------------
__global__ __launch_bounds__(256, 1) void gemm1_mma(const float* __restrict__ b1) {
    int e = blockIdx.z;
    int len = g_len[e];
    int row0 = blockIdx.y * BM;
    if (row0 >= len) return;
    int col0 = blockIdx.x * BN;

    extern __shared__ __align__(128) char smem_d[];
    uint32_t sb = smem_u32(smem_d);

    float accm[4][4][4], accc[4][4][4];
#pragma unroll
    for (int i = 0; i < 4; i++)
#pragma unroll
        for (int j = 0; j < 4; j++)
#pragma unroll
            for (int k = 0; k < 4; k++) { accm[i][j][k] = 0.f; accc[i][j][k] = 0.f; }

    gemm_core<true>(e, len, row0, col0, sb, accm, accc);

    int lane = threadIdx.x & 31, wid = threadIdx.x >> 5;
    int wm = wid & 1, wn = wid >> 1;
    const float* bb = b1 + (size_t)e * HID;
#pragma unroll
    for (int mt = 0; mt < 4; mt++) {
        int rA = row0 + wm * 64 + mt * 16 + (lane >> 2);
        int rB = rA + 8;
        bool vA = rA < len, vB = rB < len;
        size_t oA = ((size_t)e * CAPCT + rA) * HID;
        size_t oB = ((size_t)e * CAPCT + rB) * HID;
#pragma unroll
        for (int nt = 0; nt < 4; nt++) {
            int col = col0 + wn * 32 + nt * 8 + (lane & 3) * 2;
            float bv0 = bb[col], bv1 = bb[col + 1];
            if (vA) {
                float x0 = gelu_exact(accm[mt][nt][0] + accc[mt][nt][0] * INV_CORR + bv0);
                float x1 = gelu_exact(accm[mt][nt][1] + accc[mt][nt][1] * INV_CORR + bv1);
                __nv_bfloat16 h0 = __float2bfloat16(x0), h1 = __float2bfloat16(x1);
                *(uint32_t*)(g_h_hi + oA + col) = (uint32_t)__bfloat16_as_ushort(h0) |
                                                  ((uint32_t)__bfloat16_as_ushort(h1) << 16);
                *(uint16_t*)(g_h_hi8 + oA + col) = cvt_fp8x2(x1 * S_AH8, x0 * S_AH8);
                float l0 = x0 - __bfloat162float(h0), l1 = x1 - __bfloat162float(h1);
                *(uint16_t*)(g_h_lo8 + oA + col) = cvt_fp8x2(l1 * S_AL8, l0 * S_AL8);
            }
            if (vB) {
                float x0 = gelu_exact(accm[mt][nt][2] + accc[mt][nt][2] * INV_CORR + bv0);
                float x1 = gelu_exact(accm[mt][nt][3] + accc[mt][nt][3] * INV_CORR + bv1);
                __nv_bfloat16 h0 = __float2bfloat16(x0), h1 = __float2bfloat16(x1);
                *(uint32_t*)(g_h_hi + oB + col) = (uint32_t)__bfloat16_as_ushort(h0) |
                                                  ((uint32_t)__bfloat16_as_ushort(h1) << 16);
                *(uint16_t*)(g_h_hi8 + oB + col) = cvt_fp8x2(x1 * S_AH8, x0 * S_AH8);
                float l0 = x0 - __bfloat162float(h0), l1 = x1 - __bfloat162float(h1);
                *(uint16_t*)(g_h_lo8 + oB + col) = cvt_fp8x2(l1 * S_AL8, l0 * S_AL8);
            }
        }
    }
}

// ---------------- GEMM2: out[tok] += gw * (h @ W2 + b2) ----------------
__global__ __launch_bounds__(256, 1) void gemm2_mma(const float* __restrict__ b2,
                                                    float* __restrict__ out) {
    int e = blockIdx.z;
    int len = g_len[e];
    int row0 = blockIdx.y * BM;
    if (row0 >= len) return;
    int col0 = blockIdx.x * BN;

    extern __shared__ __align__(128) char smem_d[];
    uint32_t sb = smem_u32(smem_d);

    float accm[4][4][4], accc[4][4][4];
#pragma unroll
    for (int i = 0; i < 4; i++)
#pragma unroll
        for (int j = 0; j < 4; j++)
#pragma unroll
            for (int k = 0; k < 4; k++) { accm[i][j][k] = 0.f; accc[i][j][k] = 0.f; }

    gemm_core<false>(e, len, row0, col0, sb, accm, accc);

    int lane = threadIdx.x & 31, wid = threadIdx.x >> 5;
    int wm = wid & 1, wn = wid >> 1;
    const float* bb = b2 + (size_t)e * DIMSZ;
#pragma unroll
    for (int mt = 0; mt < 4; mt++) {
        int rA = row0 + wm * 64 + mt * 16 + (lane >> 2);
        int rB = rA + 8;
        bool vA = rA < len, vB = rB < len;
        int   tokA = vA ? g_tok[e * CAPCT + rA] : 0;
        float gwA  = vA ? g_gw[e * CAPCT + rA]  : 0.f;
        int   tokB = vB ? g_tok[e * CAPCT + rB] : 0;
        float gwB  = vB ? g_gw[e * CAPCT + rB]  : 0.f;
        float* oA = out + (size_t)tokA * DIMSZ;
        float* oB = out + (size_t)tokB * DIMSZ;
#pragma unroll
        for (int nt = 0; nt < 4; nt++) {
            int col = col0 + wn * 32 + nt * 8 + (lane & 3) * 2;
            float bv0 = bb[col], bv1 = bb[col + 1];
            if (vA) {
                atomicAdd(oA + col,     (accm[mt][nt][0] + accc[mt][nt][0] * INV_CORR + bv0) * gwA);
                atomicAdd(oA + col + 1, (accm[mt][nt][1] + accc[mt][nt][1] * INV_CORR + bv1) * gwA);
            }
            if (vB) {
                atomicAdd(oB + col,     (accm[mt][nt][2] + accc[mt][nt][2] * INV_CORR + bv0) * gwB);
                atomicAdd(oB + col + 1, (accm[mt][nt][3] + accc[mt][nt][3] * INV_CORR + bv1) * gwB);
            }
        }
    }
}

// ---------------- aux loss ----------------
__global__ void aux_kernel(float* out, int out_size) {
    if ((size_t)out_size <= (size_t)BTOK * DIMSZ) return;
    float proc[NEXP];
    float psum = 0.f;
#pragma unroll
    for (int e = 0; e < NEXP; e++) {
        proc[e] = fminf((float)g_count[e], (float)CAPCT);
        psum += proc[e];
    }
    float inv = 1.f / fmaxf(psum, 1.f);
    float lb = 0.f;
#pragma unroll
    for (int e = 0; e < NEXP; e++)
        lb += (g_usage[e] / (float)BTOK) * (proc[e] * inv);
    lb *= (float)NEXP;
    float zl = g_z2 / (float)BTOK;
    out[(size_t)BTOK * DIMSZ] = 0.01f * lb + 0.01f * zl;
}

// ---------------- launch ----------------
extern "C" void kernel_launch(void* const* d_in, const int* in_sizes, int n_in,
                              void* d_out, int out_size) {
    const float* x  = (const float*)d_in[0];
    const float* rw = (const float*)d_in[1];
    const float* w1 = (const float*)d_in[2];
    const float* b1 = (const float*)d_in[3];
    const float* w2 = (const float*)d_in[4];
    const float* b2 = (const float*)d_in[5];
    float* out = (float*)d_out;

    cudaFuncSetAttribute(gemm1_mma, cudaFuncAttributeMaxDynamicSharedMemorySize, SMEM_G);
    cudaFuncSetAttribute(gemm2_mma, cudaFuncAttributeMaxDynamicSharedMemorySize, SMEM_G);

    cudaMemsetAsync(out, 0, (size_t)BTOK * DIMSZ * sizeof(float), 0);
    init_kernel<<<1, 64>>>();
    conv_x_kernel<<<(BTOK * DIMSZ / 4) / 256, 256>>>(x);
    conv_tr_kernel<<<dim3(HID / 32, DIMSZ / 32, NEXP), 256>>>(w1, 0, DIMSZ, HID);
    conv_tr_kernel<<<dim3(DIMSZ / 32, HID / 32, NEXP), 256>>>(w2, 1, HID, DIMSZ);
    router_kernel<<<BTOK / 32, 256>>>(x, rw);
    select_kernel<<<NEXP, 256>>>();
    build_kernel<<<NSLOT / 256, 256>>>();
    gemm1_mma<<<dim3(HID / BN, CAPCT / BM, NEXP), 256, SMEM_G>>>(b1);
    gemm2_mma<<<dim3(DIMSZ / BN, CAPCT / BM, NEXP), 256, SMEM_G>>>(b2, out);
    aux_kernel<<<1, 1>>>(out, out_size);
}

// round 10
// speedup vs baseline: 1.6816x; 1.6816x over previous
#include <cuda_runtime.h>
#include <cuda_bf16.h>
#include <math.h>
#include <stdint.h>

// ---------------- problem constants ----------------
#define BTOK   32768
#define DIMSZ  1024
#define NEXP   8
#define TOPK   2
#define HID    4096
#define CAPCT  10240            // ceil(1.25 * 32768 * 2 / 8)
#define NSLOT  (BTOK * TOPK)    // 65536

// ---------------- GEMM tiling ----------------
#define BM 128
#define BN 128
#define BK 32                   // K elements per chunk (bf16)
#define ROWB 80                 // padded row stride bytes (64 data + 16 pad)
#define RG_A_HI 0
#define RG_A_LO 10240
#define RG_B_HI 20480
#define RG_B_LO 30720
#define STG_BYTES 40960
#define NSTAGE 3
#define SMEM_G (NSTAGE * STG_BYTES)   // 122880, dynamic (opt-in)

// ---------------- device scratch (static, no allocs) ----------------
__device__ __align__(128) __nv_bfloat16 g_x_hi[(size_t)BTOK * DIMSZ];
__device__ __align__(128) __nv_bfloat16 g_x_lo[(size_t)BTOK * DIMSZ];
__device__ __align__(128) __nv_bfloat16 g_w1t_hi[(size_t)NEXP * HID * DIMSZ]; // [e][n=hid][k=dim]
__device__ __align__(128) __nv_bfloat16 g_w1t_lo[(size_t)NEXP * HID * DIMSZ];
__device__ __align__(128) __nv_bfloat16 g_w2t_hi[(size_t)NEXP * DIMSZ * HID]; // [e][n=dim][k=hid]
__device__ __align__(128) __nv_bfloat16 g_w2t_lo[(size_t)NEXP * DIMSZ * HID];
__device__ __align__(128) __nv_bfloat16 g_h_hi[(size_t)NEXP * CAPCT * HID];
__device__ __align__(128) __nv_bfloat16 g_h_lo[(size_t)NEXP * CAPCT * HID];
__device__ __align__(128) int                g_tok[NEXP * CAPCT];
__device__ __align__(128) float              g_gw[NEXP * CAPCT];
__device__ __align__(128) int                g_topi[NSLOT];
__device__ __align__(128) float              g_topw[NSLOT];
__device__ int                g_count[NEXP];
__device__ int                g_len[NEXP];
__device__ float              g_usage[NEXP];
__device__ float              g_z2;
__device__ unsigned long long g_thr[NEXP];

// ---------------- helpers ----------------
__device__ __forceinline__ uint32_t smem_u32(const void* p) {
    uint32_t a;
    asm("{ .reg .u64 t; cvta.to.shared.u64 t, %1; cvt.u32.u64 %0, t; }" : "=r"(a) : "l"(p));
    return a;
}
__device__ __forceinline__ void cp16(uint32_t d, const void* s) {
    asm volatile("cp.async.cg.shared.global [%0], [%1], 16;" :: "r"(d), "l"(s));
}
__device__ __forceinline__ void cp_commit() { asm volatile("cp.async.commit_group;"); }
__device__ __forceinline__ void cp_wait1()  { asm volatile("cp.async.wait_group 1;"); }

__device__ __forceinline__ void ldsm4(uint32_t* r, uint32_t a) {
    asm volatile("ldmatrix.sync.aligned.m8n8.x4.shared.b16 {%0,%1,%2,%3}, [%4];"
                 : "=r"(r[0]), "=r"(r[1]), "=r"(r[2]), "=r"(r[3]) : "r"(a));
}
__device__ __forceinline__ void mma16816(float* d, const uint32_t* a, uint32_t b0, uint32_t b1) {
    asm volatile("mma.sync.aligned.m16n8k16.row.col.f32.bf16.bf16.f32 "
                 "{%0,%1,%2,%3}, {%4,%5,%6,%7}, {%8,%9}, {%0,%1,%2,%3};"
                 : "+f"(d[0]), "+f"(d[1]), "+f"(d[2]), "+f"(d[3])
                 : "r"(a[0]), "r"(a[1]), "r"(a[2]), "r"(a[3]), "r"(b0), "r"(b1));
}

__device__ __forceinline__ unsigned long long make_key(float w, int slot) {
    return ((unsigned long long)__float_as_uint(w) << 32) |
           (unsigned long long)(0xFFFFFFFFu - (unsigned)slot);
}
__device__ __forceinline__ float gelu_exact(float v) {
    return 0.5f * v * (1.0f + erff(v * 0.70710678118654752f));
}
__device__ __forceinline__ uint32_t pack_bf2(float a, float b) {
    __nv_bfloat16 h0 = __float2bfloat16(a), h1 = __float2bfloat16(b);
    return (uint32_t)__bfloat16_as_ushort(h0) | ((uint32_t)__bfloat16_as_ushort(h1) << 16);
}

// ---------------- init ----------------
__global__ void init_kernel() {
    int t = threadIdx.x;
    if (t < NEXP) { g_count[t] = 0; g_len[t] = 0; g_usage[t] = 0.f; }
    if (t == 0)   { g_z2 = 0.f; }
}

// ---------------- conversions ----------------
__global__ __launch_bounds__(256) void conv_x_kernel(const float* __restrict__ x) {
    size_t i = (size_t)blockIdx.x * 256 + threadIdx.x;        // float4 index
    float4 v = ((const float4*)x)[i];
    float f[4] = {v.x, v.y, v.z, v.w};
    uint32_t ph[2], pl[2];
#pragma unroll
    for (int q = 0; q < 2; q++) {
        float a = f[2 * q], b = f[2 * q + 1];
        __nv_bfloat16 h0 = __float2bfloat16(a), h1 = __float2bfloat16(b);
        ph[q] = (uint32_t)__bfloat16_as_ushort(h0) | ((uint32_t)__bfloat16_as_ushort(h1) << 16);
        pl[q] = pack_bf2(a - __bfloat162float(h0), b - __bfloat162float(h1));
    }
    ((uint2*)g_x_hi)[i] = make_uint2(ph[0], ph[1]);
    ((uint2*)g_x_lo)[i] = make_uint2(pl[0], pl[1]);
}

// transpose + split: src [e][K_][N_] fp32 -> dst [e][N_][K_] bf16 hi/lo
// Destination globals bound INSIDE device code (host-passed __device__ symbols
// resolve to the host shadow -> silent ATS writes on GB300; R4/R6 bug).
__global__ __launch_bounds__(256) void conv_tr_kernel(const float* __restrict__ src,
                                                      int which, int K_, int N_) {
    __nv_bfloat16* dhi = which ? g_w2t_hi : g_w1t_hi;
    __nv_bfloat16* dlo = which ? g_w2t_lo : g_w1t_lo;
    __shared__ float t[32][33];
    int e = blockIdx.z;
    src += (size_t)e * K_ * N_;
    dhi += (size_t)e * K_ * N_;
    dlo += (size_t)e * K_ * N_;
    int n0 = blockIdx.x * 32, k0 = blockIdx.y * 32;
    int tx = threadIdx.x & 31, ty = threadIdx.x >> 5;
#pragma unroll
    for (int i = 0; i < 32; i += 8)
        t[ty + i][tx] = src[(size_t)(k0 + ty + i) * N_ + n0 + tx];
    __syncthreads();
#pragma unroll
    for (int i = 0; i < 32; i += 8) {
        float v = t[tx][ty + i];
        __nv_bfloat16 h = __float2bfloat16(v);
        __nv_bfloat16 l = __float2bfloat16(v - __bfloat162float(h));
        size_t o = (size_t)(n0 + ty + i) * K_ + k0 + tx;
        dhi[o] = h; dlo[o] = l;
    }
}

// ---------------- router ----------------
__global__ __launch_bounds__(256) void router_kernel(const float* __restrict__ x,
                                                     const float* __restrict__ rw) {
    __shared__ float sW[NEXP * DIMSZ];
    __shared__ float s_usage[NEXP];
    __shared__ int   s_count[NEXP];
    __shared__ float s_z2;

    int tid = threadIdx.x;
    for (int i = tid; i < NEXP * DIMSZ; i += 256) sW[i] = rw[i];
    if (tid < NEXP) { s_usage[tid] = 0.f; s_count[tid] = 0; }
    if (tid == 0) s_z2 = 0.f;
    __syncthreads();

    int warp = tid >> 5, lane = tid & 31;
    for (int t = 0; t < 4; t++) {
        int row = blockIdx.x * 32 + warp * 4 + t;
        const float* xr = x + (size_t)row * DIMSZ;
        float acc[NEXP];
#pragma unroll
        for (int e = 0; e < NEXP; e++) acc[e] = 0.f;
        for (int i = lane; i < DIMSZ; i += 32) {
            float xv = xr[i];
#pragma unroll
            for (int e = 0; e < NEXP; e++) acc[e] = fmaf(xv, sW[e * DIMSZ + i], acc[e]);
        }
#pragma unroll
        for (int e = 0; e < NEXP; e++)
#pragma unroll
            for (int off = 16; off; off >>= 1)
                acc[e] += __shfl_xor_sync(0xFFFFFFFFu, acc[e], off);

        if (lane == 0) {
            float m = acc[0];
#pragma unroll
            for (int e = 1; e < NEXP; e++) m = fmaxf(m, acc[e]);
            float p[NEXP]; float se = 0.f;
#pragma unroll
            for (int e = 0; e < NEXP; e++) { p[e] = expf(acc[e] - m); se += p[e]; }
            float inv = 1.f / se;
#pragma unroll
            for (int e = 0; e < NEXP; e++) p[e] *= inv;
            float z = m + logf(se);

            int i0 = 0;
#pragma unroll
            for (int e = 1; e < NEXP; e++) if (acc[e] > acc[i0]) i0 = e;
            int i1 = -1;
#pragma unroll
            for (int e = 0; e < NEXP; e++)
                if (e != i0 && (i1 < 0 || acc[e] > acc[i1])) i1 = e;

            float p0 = p[i0], p1 = p[i1];
            float s = fmaxf(p0 + p1, 1e-9f);
            g_topi[row * 2 + 0] = i0; g_topw[row * 2 + 0] = p0 / s;
            g_topi[row * 2 + 1] = i1; g_topw[row * 2 + 1] = p1 / s;

            atomicAdd(&s_count[i0], 1);
            atomicAdd(&s_count[i1], 1);
#pragma unroll
            for (int e = 0; e < NEXP; e++) atomicAdd(&s_usage[e], p[e]);
            atomicAdd(&s_z2, z * z);
        }
    }
    __syncthreads();
    if (tid < NEXP) {
        atomicAdd(&g_usage[tid], s_usage[tid]);
        atomicAdd(&g_count[tid], s_count[tid]);
    }
    if (tid == 0) atomicAdd(&g_z2, s_z2);
}

// ---------------- exact capacity threshold (radix select, only on overflow) ----------------
__global__ void select_kernel() {
    int e = blockIdx.x;
    if (g_count[e] <= CAPCT) {
        if (threadIdx.x == 0) g_thr[e] = 0ULL;
        return;
    }
    __shared__ unsigned int       hist[256];
    __shared__ unsigned long long s_prefix;
    __shared__ int                s_rem;
    if (threadIdx.x == 0) { s_prefix = 0ULL; s_rem = CAPCT; }

    for (int pass = 7; pass >= 0; pass--) {
        __syncthreads();
        for (int i = threadIdx.x; i < 256; i += blockDim.x) hist[i] = 0u;
        __syncthreads();
        unsigned long long prefix = s_prefix;
        for (int s = threadIdx.x; s < NSLOT; s += blockDim.x) {
            if (g_topi[s] == e) {
                unsigned long long key = make_key(g_topw[s], s);
                bool match = (pass == 7) || ((key >> ((pass + 1) * 8)) == prefix);
                if (match)
                    atomicAdd(&hist[(unsigned)((key >> (pass * 8)) & 255ULL)], 1u);
            }
        }
        __syncthreads();
        if (threadIdx.x == 0) {
            int rem = s_rem;
            int digit = 0;
            for (int b = 255; b >= 0; b--) {
                if ((int)hist[b] >= rem) { digit = b; break; }
                rem -= (int)hist[b];
            }
            s_prefix = (s_prefix << 8) | (unsigned long long)digit;
            s_rem = rem;
        }
    }
    __syncthreads();
    if (threadIdx.x == 0) g_thr[e] = s_prefix;
}

// ---------------- build per-expert token lists ----------------
__global__ void build_kernel() {
    int s = blockIdx.x * blockDim.x + threadIdx.x;
    if (s >= NSLOT) return;
    int e = g_topi[s];
    float w = g_topw[s];
    bool keep = (g_count[e] <= CAPCT) || (make_key(w, s) >= g_thr[e]);
    if (keep) {
        int pos = atomicAdd(&g_len[e], 1);
        g_tok[e * CAPCT + pos] = s >> 1;
        g_gw[e * CAPCT + pos]  = w;
    }
}

// ======================================================================
// HMMA bf16x3 GEMM core. 128x128 CTA tile, K-chunk 32, 3-stage cp.async
// pipeline. MMA schedule is TERM-OUTERMOST: all 16 hi*hi tiles, then all
// 16 hi*lo, then all 16 lo*hi -- 16 independent accumulators between
// consecutive writes to any acc tile (breaks HMMA accumulator RAW chains).
// 8 warps: (wm,wn), wm in {0,1} x 64 rows, wn in {0..3} x 32 cols.
// ======================================================================
template <bool IS_G1>
__device__ __forceinline__ void gemm_core(int e, int len, int row0, int col0,
                                          uint32_t sb, float acc[4][4][4]) {
    int tid = threadIdx.x, lane = tid & 31, wid = tid >> 5;
    int wm = wid & 1, wn = wid >> 1;

    // load mapping: row = tid>>1 (0..127), sel = tid&1 (32B half of 64B row)
    int lrow = tid >> 1, lsel = tid & 1;
    const __nv_bfloat16 *aph, *apl, *bph, *bpl;
    int KTOT;
    if (IS_G1) {
        int gr = row0 + lrow;
        int tok = (gr < len) ? g_tok[e * CAPCT + gr] : 0;
        aph = g_x_hi + (size_t)tok * DIMSZ + lsel * 16;
        apl = g_x_lo + (size_t)tok * DIMSZ + lsel * 16;
        bph = g_w1t_hi + ((size_t)e * HID + col0 + lrow) * DIMSZ + lsel * 16;
        bpl = g_w1t_lo + ((size_t)e * HID + col0 + lrow) * DIMSZ + lsel * 16;
        KTOT = DIMSZ;
    } else {
        aph = g_h_hi + ((size_t)e * CAPCT + row0 + lrow) * HID + lsel * 16;
        apl = g_h_lo + ((size_t)e * CAPCT + row0 + lrow) * HID + lsel * 16;
        bph = g_w2t_hi + ((size_t)e * DIMSZ + col0 + lrow) * HID + lsel * 16;
        bpl = g_w2t_lo + ((size_t)e * DIMSZ + col0 + lrow) * HID + lsel * 16;
        KTOT = HID;
    }
    const int NK = KTOT / BK;
    uint32_t sdst = sb + lrow * ROWB + lsel * 32;

    auto load_stage = [&](int st, int kc) {
        uint32_t base = sdst + st * STG_BYTES;
        cp16(base + RG_A_HI,      aph + kc);
        cp16(base + RG_A_HI + 16, aph + kc + 8);
        cp16(base + RG_A_LO,      apl + kc);
        cp16(base + RG_A_LO + 16, apl + kc + 8);
        cp16(base + RG_B_HI,      bph + kc);
        cp16(base + RG_B_HI + 16, bph + kc + 8);
        cp16(base + RG_B_LO,      bpl + kc);
        cp16(base + RG_B_LO + 16, bpl + kc + 8);
    };

    load_stage(0, 0);   cp_commit();
    load_stage(1, BK);  cp_commit();

    // per-lane ldmatrix base offsets (x4: lanes 0-15 rows, lanes 16-31 +16B k-half)
    uint32_t arow = (uint32_t)(wm * 64 + (lane & 15)) * ROWB + ((lane >> 4) * 16);
    uint32_t brow = (uint32_t)(wn * 32 + (lane & 15)) * ROWB + ((lane >> 4) * 16);

    for (int c = 0; c < NK; c++) {
        int st = c % NSTAGE;
        cp_wait1();          // stage c resident (<=1 newer group outstanding)
        __syncthreads();     // also fences stage (c % NSTAGE) reads from last round
        if (c + 2 < NK) load_stage((c + 2) % NSTAGE, (c + 2) * BK);
        cp_commit();

        uint32_t sbase = sb + st * STG_BYTES;
#pragma unroll
        for (int kk = 0; kk < 2; kk++) {
            uint32_t ah[4][4], al[4][4];
#pragma unroll
            for (int mt = 0; mt < 4; mt++) {
                uint32_t ad = sbase + RG_A_HI + arow + mt * (16 * ROWB) + kk * 32;
                ldsm4(ah[mt], ad);
                ldsm4(al[mt], ad + (RG_A_LO - RG_A_HI));
            }
            uint32_t bh[2][4], bl[2][4];
#pragma unroll
            for (int j = 0; j < 2; j++) {
                uint32_t bd = sbase + RG_B_HI + brow + j * (16 * ROWB) + kk * 32;
                ldsm4(bh[j], bd);
                ldsm4(bl[j], bd + (RG_B_LO - RG_B_HI));
            }
            // term 1: hi*hi over all 16 accumulator tiles
#pragma unroll
            for (int mt = 0; mt < 4; mt++)
#pragma unroll
                for (int j = 0; j < 2; j++)
#pragma unroll
                    for (int s = 0; s < 2; s++)
                        mma16816(acc[mt][j * 2 + s], ah[mt], bh[j][s], bh[j][s + 2]);
            // term 2: hi*lo
#pragma unroll
            for (int mt = 0; mt < 4; mt++)
#pragma unroll
                for (int j = 0; j < 2; j++)
#pragma unroll
                    for (int s = 0; s < 2; s++)
                        mma16816(acc[mt][j * 2 + s], ah[mt], bl[j][s], bl[j][s + 2]);
            // term 3: lo*hi
#pragma unroll
            for (int mt = 0; mt < 4; mt++)
#pragma unroll
                for (int j = 0; j < 2; j++)
#pragma unroll
                    for (int s = 0; s < 2; s++)
                        mma16816(acc[mt][j * 2 + s], al[mt], bh[j][s], bh[j][s + 2]);
        }
    }
    __syncthreads();
}

// ---------------- GEMM1: h = gelu(gather(x) @ W1 + b1) ----------------
__global__ __launch_bounds__(256, 1) void gemm1_mma(const float* __restrict__ b1) {
    int e = blockIdx.z;
    int len = g_len[e];
    int row0 = blockIdx.y * BM;
    if (row0 >= len) return;
    int col0 = blockIdx.x * BN;

    extern __shared__ __align__(128) char smem_d[];
    uint32_t sb = smem_u32(smem_d);

    float acc[4][4][4];
#pragma unroll
    for (int i = 0; i < 4; i++)
#pragma unroll
        for (int j = 0; j < 4; j++)
#pragma unroll
            for (int k = 0; k < 4; k++) acc[i][j][k] = 0.f;

    gemm_core<true>(e, len, row0, col0, sb, acc);

    int lane = threadIdx.x & 31, wid = threadIdx.x >> 5;
    int wm = wid & 1, wn = wid >> 1;
    const float* bb = b1 + (size_t)e * HID;
#pragma unroll
    for (int mt = 0; mt < 4; mt++) {
        int rA = row0 + wm * 64 + mt * 16 + (lane >> 2);
        int rB = rA + 8;
        bool vA = rA < len, vB = rB < len;
        __nv_bfloat16* hhA = g_h_hi + ((size_t)e * CAPCT + rA) * HID;
        __nv_bfloat16* hlA = g_h_lo + ((size_t)e * CAPCT + rA) * HID;
        __nv_bfloat16* hhB = g_h_hi + ((size_t)e * CAPCT + rB) * HID;
        __nv_bfloat16* hlB = g_h_lo + ((size_t)e * CAPCT + rB) * HID;
#pragma unroll
        for (int nt = 0; nt < 4; nt++) {
            int col = col0 + wn * 32 + nt * 8 + (lane & 3) * 2;
            float bv0 = bb[col], bv1 = bb[col + 1];
            if (vA) {
                float x0 = gelu_exact(acc[mt][nt][0] + bv0);
                float x1 = gelu_exact(acc[mt][nt][1] + bv1);
                __nv_bfloat16 h0 = __float2bfloat16(x0), h1 = __float2bfloat16(x1);
                *(uint32_t*)(hhA + col) = (uint32_t)__bfloat16_as_ushort(h0) |
                                          ((uint32_t)__bfloat16_as_ushort(h1) << 16);
                *(uint32_t*)(hlA + col) = pack_bf2(x0 - __bfloat162float(h0),
                                                   x1 - __bfloat162float(h1));
            }
            if (vB) {
                float x0 = gelu_exact(acc[mt][nt][2] + bv0);
                float x1 = gelu_exact(acc[mt][nt][3] + bv1);
                __nv_bfloat16 h0 = __float2bfloat16(x0), h1 = __float2bfloat16(x1);
                *(uint32_t*)(hhB + col) = (uint32_t)__bfloat16_as_ushort(h0) |
                                          ((uint32_t)__bfloat16_as_ushort(h1) << 16);
                *(uint32_t*)(hlB + col) = pack_bf2(x0 - __bfloat162float(h0),
                                                   x1 - __bfloat162float(h1));
            }
        }
    }
}

// ---------------- GEMM2: out[tok] += gw * (h @ W2 + b2) ----------------
__global__ __launch_bounds__(256, 1) void gemm2_mma(const float* __restrict__ b2,
                                                    float* __restrict__ out) {
    int e = blockIdx.z;
    int len = g_len[e];
    int row0 = blockIdx.y * BM;
    if (row0 >= len) return;
    int col0 = blockIdx.x * BN;

    extern __shared__ __align__(128) char smem_d[];
    uint32_t sb = smem_u32(smem_d);

    float acc[4][4][4];
#pragma unroll
    for (int i = 0; i < 4; i++)
#pragma unroll
        for (int j = 0; j < 4; j++)
#pragma unroll
            for (int k = 0; k < 4; k++) acc[i][j][k] = 0.f;

    gemm_core<false>(e, len, row0, col0, sb, acc);

    int lane = threadIdx.x & 31, wid = threadIdx.x >> 5;
    int wm = wid & 1, wn = wid >> 1;
    const float* bb = b2 + (size_t)e * DIMSZ;
#pragma unroll
    for (int mt = 0; mt < 4; mt++) {
        int rA = row0 + wm * 64 + mt * 16 + (lane >> 2);
        int rB = rA + 8;
        bool vA = rA < len, vB = rB < len;
        int   tokA = vA ? g_tok[e * CAPCT + rA] : 0;
        float gwA  = vA ? g_gw[e * CAPCT + rA]  : 0.f;
        int   tokB = vB ? g_tok[e * CAPCT + rB] : 0;
        float gwB  = vB ? g_gw[e * CAPCT + rB]  : 0.f;
        float* oA = out + (size_t)tokA * DIMSZ;
        float* oB = out + (size_t)tokB * DIMSZ;
#pragma unroll
        for (int nt = 0; nt < 4; nt++) {
            int col = col0 + wn * 32 + nt * 8 + (lane & 3) * 2;
            float bv0 = bb[col], bv1 = bb[col + 1];
            if (vA) {
                atomicAdd(oA + col,     (acc[mt][nt][0] + bv0) * gwA);
                atomicAdd(oA + col + 1, (acc[mt][nt][1] + bv1) * gwA);
            }
            if (vB) {
                atomicAdd(oB + col,     (acc[mt][nt][2] + bv0) * gwB);
                atomicAdd(oB + col + 1, (acc[mt][nt][3] + bv1) * gwB);
            }
        }
    }
}

// ---------------- aux loss ----------------
__global__ void aux_kernel(float* out, int out_size) {
    if ((size_t)out_size <= (size_t)BTOK * DIMSZ) return;
    float proc[NEXP];
    float psum = 0.f;
#pragma unroll
    for (int e = 0; e < NEXP; e++) {
        proc[e] = fminf((float)g_count[e], (float)CAPCT);
        psum += proc[e];
    }
    float inv = 1.f / fmaxf(psum, 1.f);
    float lb = 0.f;
#pragma unroll
    for (int e = 0; e < NEXP; e++)
        lb += (g_usage[e] / (float)BTOK) * (proc[e] * inv);
    lb *= (float)NEXP;
    float zl = g_z2 / (float)BTOK;
    out[(size_t)BTOK * DIMSZ] = 0.01f * lb + 0.01f * zl;
}

// ---------------- launch ----------------
extern "C" void kernel_launch(void* const* d_in, const int* in_sizes, int n_in,
                              void* d_out, int out_size) {
    const float* x  = (const float*)d_in[0];
    const float* rw = (const float*)d_in[1];
    const float* w1 = (const float*)d_in[2];
    const float* b1 = (const float*)d_in[3];
    const float* w2 = (const float*)d_in[4];
    const float* b2 = (const float*)d_in[5];
    float* out = (float*)d_out;

    cudaFuncSetAttribute(gemm1_mma, cudaFuncAttributeMaxDynamicSharedMemorySize, SMEM_G);
    cudaFuncSetAttribute(gemm2_mma, cudaFuncAttributeMaxDynamicSharedMemorySize, SMEM_G);

    cudaMemsetAsync(out, 0, (size_t)BTOK * DIMSZ * sizeof(float), 0);
    init_kernel<<<1, 64>>>();
    conv_x_kernel<<<(BTOK * DIMSZ / 4) / 256, 256>>>(x);
    conv_tr_kernel<<<dim3(HID / 32, DIMSZ / 32, NEXP), 256>>>(w1, 0, DIMSZ, HID);
    conv_tr_kernel<<<dim3(DIMSZ / 32, HID / 32, NEXP), 256>>>(w2, 1, HID, DIMSZ);
    router_kernel<<<BTOK / 32, 256>>>(x, rw);
    select_kernel<<<NEXP, 256>>>();
    build_kernel<<<NSLOT / 256, 256>>>();
    gemm1_mma<<<dim3(HID / BN, CAPCT / BM, NEXP), 256, SMEM_G>>>(b1);
    gemm2_mma<<<dim3(DIMSZ / BN, CAPCT / BM, NEXP), 256, SMEM_G>>>(b2, out);
    aux_kernel<<<1, 1>>>(out, out_size);
}

// round 12
// speedup vs baseline: 2.9195x; 1.7361x over previous
#include <cuda_runtime.h>
#include <cuda_fp16.h>
#include <math.h>
#include <stdint.h>

// ---------------- problem constants ----------------
#define BTOK   32768
#define DIMSZ  1024
#define NEXP   8
#define TOPK   2
#define HID    4096
#define CAPCT  10240            // ceil(1.25 * 32768 * 2 / 8)
#define NSLOT  (BTOK * TOPK)    // 65536

// ---------------- GEMM tiling ----------------
#define BM 128
#define BN 128
#define BK 32                   // K elements per chunk (fp16)
#define ROWB 80                 // padded row stride bytes (64 data + 16 pad)
#define RG_A  0
#define RG_BH 10240
#define RG_BL 20480
#define STG_BYTES 30720
#define NSTAGE 3
#define SMEM_G (NSTAGE * STG_BYTES)   // 92160, dynamic (opt-in)

// ---------------- device scratch (static, no allocs) ----------------
__device__ __align__(128) __half g_x16[(size_t)BTOK * DIMSZ];
__device__ __align__(128) __half g_w1t_h[(size_t)NEXP * HID * DIMSZ]; // [e][n=hid][k=dim]
__device__ __align__(128) __half g_w1t_l[(size_t)NEXP * HID * DIMSZ];
__device__ __align__(128) __half g_w2t_h[(size_t)NEXP * DIMSZ * HID]; // [e][n=dim][k=hid]
__device__ __align__(128) __half g_w2t_l[(size_t)NEXP * DIMSZ * HID];
__device__ __align__(128) __half g_h16[(size_t)NEXP * CAPCT * HID];
__device__ __align__(128) int                g_tok[NEXP * CAPCT];
__device__ __align__(128) float              g_gw[NEXP * CAPCT];
__device__ __align__(128) int                g_topi[NSLOT];
__device__ __align__(128) float              g_topw[NSLOT];
__device__ int                g_count[NEXP];
__device__ int                g_len[NEXP];
__device__ float              g_usage[NEXP];
__device__ float              g_z2;
__device__ unsigned long long g_thr[NEXP];

// ---------------- helpers ----------------
__device__ __forceinline__ uint32_t smem_u32(const void* p) {
    uint32_t a;
    asm("{ .reg .u64 t; cvta.to.shared.u64 t, %1; cvt.u32.u64 %0, t; }" : "=r"(a) : "l"(p));
    return a;
}
__device__ __forceinline__ void cp16(uint32_t d, const void* s) {
    asm volatile("cp.async.cg.shared.global [%0], [%1], 16;" :: "r"(d), "l"(s));
}
__device__ __forceinline__ void cp_commit() { asm volatile("cp.async.commit_group;"); }
__device__ __forceinline__ void cp_wait1()  { asm volatile("cp.async.wait_group 1;"); }

__device__ __forceinline__ void ldsm4(uint32_t* r, uint32_t a) {
    asm volatile("ldmatrix.sync.aligned.m8n8.x4.shared.b16 {%0,%1,%2,%3}, [%4];"
                 : "=r"(r[0]), "=r"(r[1]), "=r"(r[2]), "=r"(r[3]) : "r"(a));
}
__device__ __forceinline__ void mma_f16(float* d, const uint32_t* a, uint32_t b0, uint32_t b1) {
    asm volatile("mma.sync.aligned.m16n8k16.row.col.f32.f16.f16.f32 "
                 "{%0,%1,%2,%3}, {%4,%5,%6,%7}, {%8,%9}, {%0,%1,%2,%3};"
                 : "+f"(d[0]), "+f"(d[1]), "+f"(d[2]), "+f"(d[3])
                 : "r"(a[0]), "r"(a[1]), "r"(a[2]), "r"(a[3]), "r"(b0), "r"(b1));
}

__device__ __forceinline__ unsigned long long make_key(float w, int slot) {
    return ((unsigned long long)__float_as_uint(w) << 32) |
           (unsigned long long)(0xFFFFFFFFu - (unsigned)slot);
}
__device__ __forceinline__ float gelu_exact(float v) {
    return 0.5f * v * (1.0f + erff(v * 0.70710678118654752f));
}

// ---------------- init ----------------
__global__ void init_kernel() {
    int t = threadIdx.x;
    if (t < NEXP) { g_count[t] = 0; g_len[t] = 0; g_usage[t] = 0.f; }
    if (t == 0)   { g_z2 = 0.f; }
}

// ---------------- conversions ----------------
__global__ __launch_bounds__(256) void conv_x_kernel(const float* __restrict__ x) {
    size_t i = (size_t)blockIdx.x * 256 + threadIdx.x;        // float4 index
    float4 v = ((const float4*)x)[i];
    __half2 p0 = __floats2half2_rn(v.x, v.y);
    __half2 p1 = __floats2half2_rn(v.z, v.w);
    ((__half2*)g_x16)[i * 2 + 0] = p0;
    ((__half2*)g_x16)[i * 2 + 1] = p1;
}

// transpose + split: src [e][K_][N_] fp32 -> dst [e][N_][K_] fp16 hi/lo
// Destination globals bound INSIDE device code (host-passed __device__ symbols
// resolve to the host shadow -> silent ATS writes on GB300; R4/R6 bug).
__global__ __launch_bounds__(256) void conv_tr_kernel(const float* __restrict__ src,
                                                      int which, int K_, int N_) {
    __half* dhi = which ? g_w2t_h : g_w1t_h;
    __half* dlo = which ? g_w2t_l : g_w1t_l;
    __shared__ float t[32][33];
    int e = blockIdx.z;
    src += (size_t)e * K_ * N_;
    dhi += (size_t)e * K_ * N_;
    dlo += (size_t)e * K_ * N_;
    int n0 = blockIdx.x * 32, k0 = blockIdx.y * 32;
    int tx = threadIdx.x & 31, ty = threadIdx.x >> 5;
#pragma unroll
    for (int i = 0; i < 32; i += 8)
        t[ty + i][tx] = src[(size_t)(k0 + ty + i) * N_ + n0 + tx];
    __syncthreads();
#pragma unroll
    for (int i = 0; i < 32; i += 8) {
        float v = t[tx][ty + i];
        __half h = __float2half_rn(v);
        __half l = __float2half_rn(v - __half2float(h));
        size_t o = (size_t)(n0 + ty + i) * K_ + k0 + tx;
        dhi[o] = h; dlo[o] = l;
    }
}

// ---------------- router ----------------
__global__ __launch_bounds__(256) void router_kernel(const float* __restrict__ x,
                                                     const float* __restrict__ rw) {
    __shared__ float sW[NEXP * DIMSZ];
    __shared__ float s_usage[NEXP];
    __shared__ int   s_count[NEXP];
    __shared__ float s_z2;

    int tid = threadIdx.x;
    for (int i = tid; i < NEXP * DIMSZ; i += 256) sW[i] = rw[i];
    if (tid < NEXP) { s_usage[tid] = 0.f; s_count[tid] = 0; }
    if (tid == 0) s_z2 = 0.f;
    __syncthreads();

    int warp = tid >> 5, lane = tid & 31;
    for (int t = 0; t < 4; t++) {
        int row = blockIdx.x * 32 + warp * 4 + t;
        const float* xr = x + (size_t)row * DIMSZ;
        float acc[NEXP];
#pragma unroll
        for (int e = 0; e < NEXP; e++) acc[e] = 0.f;
        for (int i = lane; i < DIMSZ; i += 32) {
            float xv = xr[i];
#pragma unroll
            for (int e = 0; e < NEXP; e++) acc[e] = fmaf(xv, sW[e * DIMSZ + i], acc[e]);
        }
#pragma unroll
        for (int e = 0; e < NEXP; e++)
#pragma unroll
            for (int off = 16; off; off >>= 1)
                acc[e] += __shfl_xor_sync(0xFFFFFFFFu, acc[e], off);

        if (lane == 0) {
            float m = acc[0];
#pragma unroll
            for (int e = 1; e < NEXP; e++) m = fmaxf(m, acc[e]);
            float p[NEXP]; float se = 0.f;
#pragma unroll
            for (int e = 0; e < NEXP; e++) { p[e] = expf(acc[e] - m); se += p[e]; }
            float inv = 1.f / se;
#pragma unroll
            for (int e = 0; e < NEXP; e++) p[e] *= inv;
            float z = m + logf(se);

            int i0 = 0;
#pragma unroll
            for (int e = 1; e < NEXP; e++) if (acc[e] > acc[i0]) i0 = e;
            int i1 = -1;
#pragma unroll
            for (int e = 0; e < NEXP; e++)
                if (e != i0 && (i1 < 0 || acc[e] > acc[i1])) i1 = e;

            float p0 = p[i0], p1 = p[i1];
            float s = fmaxf(p0 + p1, 1e-9f);
            g_topi[row * 2 + 0] = i0; g_topw[row * 2 + 0] = p0 / s;
            g_topi[row * 2 + 1] = i1; g_topw[row * 2 + 1] = p1 / s;

            atomicAdd(&s_count[i0], 1);
            atomicAdd(&s_count[i1], 1);
#pragma unroll
            for (int e = 0; e < NEXP; e++) atomicAdd(&s_usage[e], p[e]);
            atomicAdd(&s_z2, z * z);
        }
    }
    __syncthreads();
    if (tid < NEXP) {
        atomicAdd(&g_usage[tid], s_usage[tid]);
        atomicAdd(&g_count[tid], s_count[tid]);
    }
    if (tid == 0) atomicAdd(&g_z2, s_z2);
}

// ---------------- exact capacity threshold (radix select, only on overflow) ----------------
__global__ void select_kernel() {
    int e = blockIdx.x;
    if (g_count[e] <= CAPCT) {
        if (threadIdx.x == 0) g_thr[e] = 0ULL;
        return;
    }
    __shared__ unsigned int       hist[256];
    __shared__ unsigned long long s_prefix;
    __shared__ int                s_rem;
    if (threadIdx.x == 0) { s_prefix = 0ULL; s_rem = CAPCT; }

    for (int pass = 7; pass >= 0; pass--) {
        __syncthreads();
        for (int i = threadIdx.x; i < 256; i += blockDim.x) hist[i] = 0u;
        __syncthreads();
        unsigned long long prefix = s_prefix;
        for (int s = threadIdx.x; s < NSLOT; s += blockDim.x) {
            if (g_topi[s] == e) {
                unsigned long long key = make_key(g_topw[s], s);
                bool match = (pass == 7) || ((key >> ((pass + 1) * 8)) == prefix);
                if (match)
                    atomicAdd(&hist[(unsigned)((key >> (pass * 8)) & 255ULL)], 1u);
            }
        }
        __syncthreads();
        if (threadIdx.x == 0) {
            int rem = s_rem;
            int digit = 0;
            for (int b = 255; b >= 0; b--) {
                if ((int)hist[b] >= rem) { digit = b; break; }
                rem -= (int)hist[b];
            }
            s_prefix = (s_prefix << 8) | (unsigned long long)digit;
            s_rem = rem;
        }
    }
    __syncthreads();
    if (threadIdx.x == 0) g_thr[e] = s_prefix;
}

// ---------------- build per-expert token lists ----------------
__global__ void build_kernel() {
    int s = blockIdx.x * blockDim.x + threadIdx.x;
    if (s >= NSLOT) return;
    int e = g_topi[s];
    float w = g_topw[s];
    bool keep = (g_count[e] <= CAPCT) || (make_key(w, s) >= g_thr[e]);
    if (keep) {
        int pos = atomicAdd(&g_len[e], 1);
        g_tok[e * CAPCT + pos] = s >> 1;
        g_gw[e * CAPCT + pos]  = w;
    }
}

// ======================================================================
// HMMA fp16x2 GEMM core: acc = a16*whi + a16*wlo (weights split hi/lo,
// activations single fp16; 64 HMMA/warp/chunk vs bf16x3's 96).
// 128x128 CTA tile, K-chunk 32, 3-stage cp.async pipeline.
// 8 warps: (wm,wn), wm in {0,1} x 64 rows, wn in {0..3} x 32 cols.
// ======================================================================
template <bool IS_G1>
__device__ __forceinline__ void gemm_core(int e, int len, int row0, int col0,
                                          uint32_t sb, float acc[4][4][4]) {
    int tid = threadIdx.x, lane = tid & 31, wid = tid >> 5;
    int wm = wid & 1, wn = wid >> 1;

    // load mapping: row = tid>>1 (0..127), sel = tid&1 (32B half of 64B row)
    int lrow = tid >> 1, lsel = tid & 1;
    const __half *ap, *bph, *bpl;
    int KTOT;
    if (IS_G1) {
        int gr = row0 + lrow;
        int tok = (gr < len) ? g_tok[e * CAPCT + gr] : 0;
        ap  = g_x16 + (size_t)tok * DIMSZ + lsel * 16;
        bph = g_w1t_h + ((size_t)e * HID + col0 + lrow) * DIMSZ + lsel * 16;
        bpl = g_w1t_l + ((size_t)e * HID + col0 + lrow) * DIMSZ + lsel * 16;
        KTOT = DIMSZ;
    } else {
        ap  = g_h16 + ((size_t)e * CAPCT + row0 + lrow) * HID + lsel * 16;
        bph = g_w2t_h + ((size_t)e * DIMSZ + col0 + lrow) * HID + lsel * 16;
        bpl = g_w2t_l + ((size_t)e * DIMSZ + col0 + lrow) * HID + lsel * 16;
        KTOT = HID;
    }
    const int NK = KTOT / BK;
    uint32_t sdst = sb + lrow * ROWB + lsel * 32;

    auto load_stage = [&](int st, int kc) {
        uint32_t base = sdst + st * STG_BYTES;
        cp16(base + RG_A,       ap + kc);
        cp16(base + RG_A  + 16, ap + kc + 8);
        cp16(base + RG_BH,      bph + kc);
        cp16(base + RG_BH + 16, bph + kc + 8);
        cp16(base + RG_BL,      bpl + kc);
        cp16(base + RG_BL + 16, bpl + kc + 8);
    };

    load_stage(0, 0);   cp_commit();
    load_stage(1, BK);  cp_commit();

    // per-lane ldmatrix base offsets (x4: lanes 0-15 rows, lanes 16-31 +16B k-half)
    uint32_t arow = (uint32_t)(wm * 64 + (lane & 15)) * ROWB + ((lane >> 4) * 16);
    uint32_t brow = (uint32_t)(wn * 32 + (lane & 15)) * ROWB + ((lane >> 4) * 16);

    for (int c = 0; c < NK; c++) {
        int st = c % NSTAGE;
        cp_wait1();          // stage c resident (<=1 newer group outstanding)
        __syncthreads();     // also fences stage (c % NSTAGE) reads from last round
        if (c + 2 < NK) load_stage((c + 2) % NSTAGE, (c + 2) * BK);
        cp_commit();

        uint32_t sbase = sb + st * STG_BYTES;
#pragma unroll
        for (int kk = 0; kk < 2; kk++) {
            uint32_t ah[4][4];
#pragma unroll
            for (int mt = 0; mt < 4; mt++)
                ldsm4(ah[mt], sbase + RG_A + arow + mt * (16 * ROWB) + kk * 32);
            uint32_t bh[2][4], bl[2][4];
#pragma unroll
            for (int j = 0; j < 2; j++) {
                uint32_t bd = sbase + RG_BH + brow + j * (16 * ROWB) + kk * 32;
                ldsm4(bh[j], bd);
                ldsm4(bl[j], bd + (RG_BL - RG_BH));
            }
            // term 1: a * w_hi
#pragma unroll
            for (int mt = 0; mt < 4; mt++)
#pragma unroll
                for (int j = 0; j < 2; j++)
#pragma unroll
                    for (int s = 0; s < 2; s++)
                        mma_f16(acc[mt][j * 2 + s], ah[mt], bh[j][s], bh[j][s + 2]);
            // term 2: a * w_lo
#pragma unroll
            for (int mt = 0; mt < 4; mt++)
#pragma unroll
                for (int j = 0; j < 2; j++)
#pragma unroll
                    for (int s = 0; s < 2; s++)
                        mma_f16(acc[mt][j * 2 + s], ah[mt], bl[j][s], bl[j][s + 2]);
        }
    }
    __syncthreads();
}

// ---------------- GEMM1: h = gelu(gather(x) @ W1 + b1) ----------------
__global__ __launch_bounds__(256, 1) void gemm1_mma(const float* __restrict__ b1) {
    int e = blockIdx.z;
    int len = g_len[e];
    int row0 = blockIdx.y * BM;
    if (row0 >= len) return;
    int col0 = blockIdx.x * BN;

    extern __shared__ __align__(128) char smem_d[];
    uint32_t sb = smem_u32(smem_d);

    float acc[4][4][4];
#pragma unroll
    for (int i = 0; i < 4; i++)
#pragma unroll
        for (int j = 0; j < 4; j++)
#pragma unroll
            for (int k = 0; k < 4; k++) acc[i][j][k] = 0.f;

    gemm_core<true>(e, len, row0, col0, sb, acc);

    int lane = threadIdx.x & 31, wid = threadIdx.x >> 5;
    int wm = wid & 1, wn = wid >> 1;
    const float* bb = b1 + (size_t)e * HID;
#pragma unroll
    for (int mt = 0; mt < 4; mt++) {
        int rA = row0 + wm * 64 + mt * 16 + (lane >> 2);
        int rB = rA + 8;
        bool vA = rA < len, vB = rB < len;
        __half* hA = g_h16 + ((size_t)e * CAPCT + rA) * HID;
        __half* hB = g_h16 + ((size_t)e * CAPCT + rB) * HID;
#pragma unroll
        for (int nt = 0; nt < 4; nt++) {
            int col = col0 + wn * 32 + nt * 8 + (lane & 3) * 2;
            float bv0 = bb[col], bv1 = bb[col + 1];
            if (vA) {
                float x0 = gelu_exact(acc[mt][nt][0] + bv0);
                float x1 = gelu_exact(acc[mt][nt][1] + bv1);
                *(__half2*)(hA + col) = __floats2half2_rn(x0, x1);
            }
            if (vB) {
                float x0 = gelu_exact(acc[mt][nt][2] + bv0);
                float x1 = gelu_exact(acc[mt][nt][3] + bv1);
                *(__half2*)(hB + col) = __floats2half2_rn(x0, x1);
            }
        }
    }
}

// ---------------- GEMM2: out[tok] += gw * (h @ W2 + b2) ----------------
__global__ __launch_bounds__(256, 1) void gemm2_mma(const float* __restrict__ b2,
                                                    float* __restrict__ out) {
    int e = blockIdx.z;
    int len = g_len[e];
    int row0 = blockIdx.y * BM;
    if (row0 >= len) return;
    int col0 = blockIdx.x * BN;

    extern __shared__ __align__(128) char smem_d[];
    uint32_t sb = smem_u32(smem_d);

    float acc[4][4][4];
#pragma unroll
    for (int i = 0; i < 4; i++)
#pragma unroll
        for (int j = 0; j < 4; j++)
#pragma unroll
            for (int k = 0; k < 4; k++) acc[i][j][k] = 0.f;

    gemm_core<false>(e, len, row0, col0, sb, acc);

    int lane = threadIdx.x & 31, wid = threadIdx.x >> 5;
    int wm = wid & 1, wn = wid >> 1;
    const float* bb = b2 + (size_t)e * DIMSZ;
#pragma unroll
    for (int mt = 0; mt < 4; mt++) {
        int rA = row0 + wm * 64 + mt * 16 + (lane >> 2);
        int rB = rA + 8;
        bool vA = rA < len, vB = rB < len;
        int   tokA = vA ? g_tok[e * CAPCT + rA] : 0;
        float gwA  = vA ? g_gw[e * CAPCT + rA]  : 0.f;
        int   tokB = vB ? g_tok[e * CAPCT + rB] : 0;
        float gwB  = vB ? g_gw[e * CAPCT + rB]  : 0.f;
        float* oA = out + (size_t)tokA * DIMSZ;
        float* oB = out + (size_t)tokB * DIMSZ;
#pragma unroll
        for (int nt = 0; nt < 4; nt++) {
            int col = col0 + wn * 32 + nt * 8 + (lane & 3) * 2;
            float bv0 = bb[col], bv1 = bb[col + 1];
            if (vA) {
                atomicAdd(oA + col,     (acc[mt][nt][0] + bv0) * gwA);
                atomicAdd(oA + col + 1, (acc[mt][nt][1] + bv1) * gwA);
            }
            if (vB) {
                atomicAdd(oB + col,     (acc[mt][nt][2] + bv0) * gwB);
                atomicAdd(oB + col + 1, (acc[mt][nt][3] + bv1) * gwB);
            }
        }
    }
}

// ---------------- aux loss ----------------
__global__ void aux_kernel(float* out, int out_size) {
    if ((size_t)out_size <= (size_t)BTOK * DIMSZ) return;
    float proc[NEXP];
    float psum = 0.f;
#pragma unroll
    for (int e = 0; e < NEXP; e++) {
        proc[e] = fminf((float)g_count[e], (float)CAPCT);
        psum += proc[e];
    }
    float inv = 1.f / fmaxf(psum, 1.f);
    float lb = 0.f;
#pragma unroll
    for (int e = 0; e < NEXP; e++)
        lb += (g_usage[e] / (float)BTOK) * (proc[e] * inv);
    lb *= (float)NEXP;
    float zl = g_z2 / (float)BTOK;
    out[(size_t)BTOK * DIMSZ] = 0.01f * lb + 0.01f * zl;
}

// ---------------- launch ----------------
extern "C" void kernel_launch(void* const* d_in, const int* in_sizes, int n_in,
                              void* d_out, int out_size) {
    const float* x  = (const float*)d_in[0];
    const float* rw = (const float*)d_in[1];
    const float* w1 = (const float*)d_in[2];
    const float* b1 = (const float*)d_in[3];
    const float* w2 = (const float*)d_in[4];
    const float* b2 = (const float*)d_in[5];
    float* out = (float*)d_out;

    cudaFuncSetAttribute(gemm1_mma, cudaFuncAttributeMaxDynamicSharedMemorySize, SMEM_G);
    cudaFuncSetAttribute(gemm2_mma, cudaFuncAttributeMaxDynamicSharedMemorySize, SMEM_G);

    cudaMemsetAsync(out, 0, (size_t)BTOK * DIMSZ * sizeof(float), 0);
    init_kernel<<<1, 64>>>();
    conv_x_kernel<<<(BTOK * DIMSZ / 4) / 256, 256>>>(x);
    conv_tr_kernel<<<dim3(HID / 32, DIMSZ / 32, NEXP), 256>>>(w1, 0, DIMSZ, HID);
    conv_tr_kernel<<<dim3(DIMSZ / 32, HID / 32, NEXP), 256>>>(w2, 1, HID, DIMSZ);
    router_kernel<<<BTOK / 32, 256>>>(x, rw);
    select_kernel<<<NEXP, 256>>>();
    build_kernel<<<NSLOT / 256, 256>>>();
    gemm1_mma<<<dim3(HID / BN, CAPCT / BM, NEXP), 256, SMEM_G>>>(b1);
    gemm2_mma<<<dim3(DIMSZ / BN, CAPCT / BM, NEXP), 256, SMEM_G>>>(b2, out);
    aux_kernel<<<1, 1>>>(out, out_size);
}

// round 13
// speedup vs baseline: 4.8219x; 1.6516x over previous
#include <cuda_runtime.h>
#include <cuda_fp16.h>
#include <math.h>
#include <stdint.h>

// ---------------- problem constants ----------------
#define BTOK   32768
#define DIMSZ  1024
#define NEXP   8
#define TOPK   2
#define HID    4096
#define CAPCT  10240            // ceil(1.25 * 32768 * 2 / 8)
#define NSLOT  (BTOK * TOPK)    // 65536

// ---------------- GEMM tiling ----------------
#define BM 128
#define BN 128
#define BK 32                   // K elements per chunk (fp16)
#define ROWB 80                 // padded row stride bytes (64 data + 16 pad)
#define RG_A  0
#define RG_B  10240
#define STG_BYTES 20480
#define NSTAGE 3
#define SMEM_G (NSTAGE * STG_BYTES)   // 61440, dynamic (opt-in)

// ---------------- device scratch (static, no allocs) ----------------
__device__ __align__(128) __half g_x16[(size_t)BTOK * DIMSZ];
__device__ __align__(128) __half g_w1t[(size_t)NEXP * HID * DIMSZ]; // [e][n=hid][k=dim]
__device__ __align__(128) __half g_w2t[(size_t)NEXP * DIMSZ * HID]; // [e][n=dim][k=hid]
__device__ __align__(128) __half g_h16[(size_t)NEXP * CAPCT * HID];
__device__ __align__(128) int                g_tok[NEXP * CAPCT];
__device__ __align__(128) float              g_gw[NEXP * CAPCT];
__device__ __align__(128) int                g_topi[NSLOT];
__device__ __align__(128) float              g_topw[NSLOT];
__device__ int                g_count[NEXP];
__device__ int                g_len[NEXP];
__device__ float              g_usage[NEXP];
__device__ float              g_z2;
__device__ unsigned long long g_thr[NEXP];

// ---------------- helpers ----------------
__device__ __forceinline__ uint32_t smem_u32(const void* p) {
    uint32_t a;
    asm("{ .reg .u64 t; cvta.to.shared.u64 t, %1; cvt.u32.u64 %0, t; }" : "=r"(a) : "l"(p));
    return a;
}
__device__ __forceinline__ void cp16(uint32_t d, const void* s) {
    asm volatile("cp.async.cg.shared.global [%0], [%1], 16;" :: "r"(d), "l"(s));
}
__device__ __forceinline__ void cp_commit() { asm volatile("cp.async.commit_group;"); }
__device__ __forceinline__ void cp_wait1()  { asm volatile("cp.async.wait_group 1;"); }

__device__ __forceinline__ void ldsm4(uint32_t* r, uint32_t a) {
    asm volatile("ldmatrix.sync.aligned.m8n8.x4.shared.b16 {%0,%1,%2,%3}, [%4];"
                 : "=r"(r[0]), "=r"(r[1]), "=r"(r[2]), "=r"(r[3]) : "r"(a));
}
__device__ __forceinline__ void mma_f16(float* d, const uint32_t* a, uint32_t b0, uint32_t b1) {
    asm volatile("mma.sync.aligned.m16n8k16.row.col.f32.f16.f16.f32 "
                 "{%0,%1,%2,%3}, {%4,%5,%6,%7}, {%8,%9}, {%0,%1,%2,%3};"
                 : "+f"(d[0]), "+f"(d[1]), "+f"(d[2]), "+f"(d[3])
                 : "r"(a[0]), "r"(a[1]), "r"(a[2]), "r"(a[3]), "r"(b0), "r"(b1));
}

__device__ __forceinline__ unsigned long long make_key(float w, int slot) {
    return ((unsigned long long)__float_as_uint(w) << 32) |
           (unsigned long long)(0xFFFFFFFFu - (unsigned)slot);
}
__device__ __forceinline__ float gelu_exact(float v) {
    return 0.5f * v * (1.0f + erff(v * 0.70710678118654752f));
}

// ---------------- init ----------------
__global__ void init_kernel() {
    int t = threadIdx.x;
    if (t < NEXP) { g_count[t] = 0; g_len[t] = 0; g_usage[t] = 0.f; }
    if (t == 0)   { g_z2 = 0.f; }
}

// ---------------- conversions ----------------
__global__ __launch_bounds__(256) void conv_x_kernel(const float* __restrict__ x) {
    size_t i = (size_t)blockIdx.x * 256 + threadIdx.x;        // float4 index
    float4 v = ((const float4*)x)[i];
    __half2 p0 = __floats2half2_rn(v.x, v.y);
    __half2 p1 = __floats2half2_rn(v.z, v.w);
    ((__half2*)g_x16)[i * 2 + 0] = p0;
    ((__half2*)g_x16)[i * 2 + 1] = p1;
}

// transpose: src [e][K_][N_] fp32 -> dst [e][N_][K_] fp16
// Destination globals bound INSIDE device code (host-passed __device__ symbols
// resolve to the host shadow -> silent ATS writes on GB300; R4/R6 bug).
__global__ __launch_bounds__(256) void conv_tr_kernel(const float* __restrict__ src,
                                                      int which, int K_, int N_) {
    __half* dst = which ? g_w2t : g_w1t;
    __shared__ float t[32][33];
    int e = blockIdx.z;
    src += (size_t)e * K_ * N_;
    dst += (size_t)e * K_ * N_;
    int n0 = blockIdx.x * 32, k0 = blockIdx.y * 32;
    int tx = threadIdx.x & 31, ty = threadIdx.x >> 5;
#pragma unroll
    for (int i = 0; i < 32; i += 8)
        t[ty + i][tx] = src[(size_t)(k0 + ty + i) * N_ + n0 + tx];
    __syncthreads();
#pragma unroll
    for (int i = 0; i < 32; i += 8) {
        float v = t[tx][ty + i];
        dst[(size_t)(n0 + ty + i) * K_ + k0 + tx] = __float2half_rn(v);
    }
}

// ---------------- router ----------------
__global__ __launch_bounds__(256) void router_kernel(const float* __restrict__ x,
                                                     const float* __restrict__ rw) {
    __shared__ float sW[NEXP * DIMSZ];
    __shared__ float s_usage[NEXP];
    __shared__ int   s_count[NEXP];
    __shared__ float s_z2;

    int tid = threadIdx.x;
    for (int i = tid; i < NEXP * DIMSZ; i += 256) sW[i] = rw[i];
    if (tid < NEXP) { s_usage[tid] = 0.f; s_count[tid] = 0; }
    if (tid == 0) s_z2 = 0.f;
    __syncthreads();

    int warp = tid >> 5, lane = tid & 31;
    for (int t = 0; t < 4; t++) {
        int row = blockIdx.x * 32 + warp * 4 + t;
        const float* xr = x + (size_t)row * DIMSZ;
        float acc[NEXP];
#pragma unroll
        for (int e = 0; e < NEXP; e++) acc[e] = 0.f;
        for (int i = lane; i < DIMSZ; i += 32) {
            float xv = xr[i];
#pragma unroll
            for (int e = 0; e < NEXP; e++) acc[e] = fmaf(xv, sW[e * DIMSZ + i], acc[e]);
        }
#pragma unroll
        for (int e = 0; e < NEXP; e++)
#pragma unroll
            for (int off = 16; off; off >>= 1)
                acc[e] += __shfl_xor_sync(0xFFFFFFFFu, acc[e], off);

        if (lane == 0) {
            float m = acc[0];
#pragma unroll
            for (int e = 1; e < NEXP; e++) m = fmaxf(m, acc[e]);
            float p[NEXP]; float se = 0.f;
#pragma unroll
            for (int e = 0; e < NEXP; e++) { p[e] = expf(acc[e] - m); se += p[e]; }
            float inv = 1.f / se;
#pragma unroll
            for (int e = 0; e < NEXP; e++) p[e] *= inv;
            float z = m + logf(se);

            int i0 = 0;
#pragma unroll
            for (int e = 1; e < NEXP; e++) if (acc[e] > acc[i0]) i0 = e;
            int i1 = -1;
#pragma unroll
            for (int e = 0; e < NEXP; e++)
                if (e != i0 && (i1 < 0 || acc[e] > acc[i1])) i1 = e;

            float p0 = p[i0], p1 = p[i1];
            float s = fmaxf(p0 + p1, 1e-9f);
            g_topi[row * 2 + 0] = i0; g_topw[row * 2 + 0] = p0 / s;
            g_topi[row * 2 + 1] = i1; g_topw[row * 2 + 1] = p1 / s;

            atomicAdd(&s_count[i0], 1);
            atomicAdd(&s_count[i1], 1);
#pragma unroll
            for (int e = 0; e < NEXP; e++) atomicAdd(&s_usage[e], p[e]);
            atomicAdd(&s_z2, z * z);
        }
    }
    __syncthreads();
    if (tid < NEXP) {
        atomicAdd(&g_usage[tid], s_usage[tid]);
        atomicAdd(&g_count[tid], s_count[tid]);
    }
    if (tid == 0) atomicAdd(&g_z2, s_z2);
}

// ---------------- exact capacity threshold (radix select, only on overflow) ----------------
__global__ void select_kernel() {
    int e = blockIdx.x;
    if (g_count[e] <= CAPCT) {
        if (threadIdx.x == 0) g_thr[e] = 0ULL;
        return;
    }
    __shared__ unsigned int       hist[256];
    __shared__ unsigned long long s_prefix;
    __shared__ int                s_rem;
    if (threadIdx.x == 0) { s_prefix = 0ULL; s_rem = CAPCT; }

    for (int pass = 7; pass >= 0; pass--) {
        __syncthreads();
        for (int i = threadIdx.x; i < 256; i += blockDim.x) hist[i] = 0u;
        __syncthreads();
        unsigned long long prefix = s_prefix;
        for (int s = threadIdx.x; s < NSLOT; s += blockDim.x) {
            if (g_topi[s] == e) {
                unsigned long long key = make_key(g_topw[s], s);
                bool match = (pass == 7) || ((key >> ((pass + 1) * 8)) == prefix);
                if (match)
                    atomicAdd(&hist[(unsigned)((key >> (pass * 8)) & 255ULL)], 1u);
            }
        }
        __syncthreads();
        if (threadIdx.x == 0) {
            int rem = s_rem;
            int digit = 0;
            for (int b = 255; b >= 0; b--) {
                if ((int)hist[b] >= rem) { digit = b; break; }
                rem -= (int)hist[b];
            }
            s_prefix = (s_prefix << 8) | (unsigned long long)digit;
            s_rem = rem;
        }
    }
    __syncthreads();
    if (threadIdx.x == 0) g_thr[e] = s_prefix;
}

// ---------------- build per-expert token lists ----------------
__global__ void build_kernel() {
    int s = blockIdx.x * blockDim.x + threadIdx.x;
    if (s >= NSLOT) return;
    int e = g_topi[s];
    float w = g_topw[s];
    bool keep = (g_count[e] <= CAPCT) || (make_key(w, s) >= g_thr[e]);
    if (keep) {
        int pos = atomicAdd(&g_len[e], 1);
        g_tok[e * CAPCT + pos] = s >> 1;
        g_gw[e * CAPCT + pos]  = w;
    }
}

// ======================================================================
// Plain fp16 HMMA GEMM core (fp32 accumulate): 32 HMMA/warp/chunk.
// 128x128 CTA tile, K-chunk 32, 3-stage cp.async pipeline.
// 8 warps: (wm,wn), wm in {0,1} x 64 rows, wn in {0..3} x 32 cols.
// ======================================================================
template <bool IS_G1>
__device__ __forceinline__ void gemm_core(int e, int len, int row0, int col0,
                                          uint32_t sb, float acc[4][4][4]) {
    int tid = threadIdx.x, lane = tid & 31, wid = tid >> 5;
    int wm = wid & 1, wn = wid >> 1;

    // load mapping: row = tid>>1 (0..127), sel = tid&1 (32B half of 64B row)
    int lrow = tid >> 1, lsel = tid & 1;
    const __half *ap, *bp;
    int KTOT;
    if (IS_G1) {
        int gr = row0 + lrow;
        int tok = (gr < len) ? g_tok[e * CAPCT + gr] : 0;
        ap = g_x16 + (size_t)tok * DIMSZ + lsel * 16;
        bp = g_w1t + ((size_t)e * HID + col0 + lrow) * DIMSZ + lsel * 16;
        KTOT = DIMSZ;
    } else {
        ap = g_h16 + ((size_t)e * CAPCT + row0 + lrow) * HID + lsel * 16;
        bp = g_w2t + ((size_t)e * DIMSZ + col0 + lrow) * HID + lsel * 16;
        KTOT = HID;
    }
    const int NK = KTOT / BK;
    uint32_t sdst = sb + lrow * ROWB + lsel * 32;

    auto load_stage = [&](int st, int kc) {
        uint32_t base = sdst + st * STG_BYTES;
        cp16(base + RG_A,      ap + kc);
        cp16(base + RG_A + 16, ap + kc + 8);
        cp16(base + RG_B,      bp + kc);
        cp16(base + RG_B + 16, bp + kc + 8);
    };

    load_stage(0, 0);   cp_commit();
    load_stage(1, BK);  cp_commit();

    // per-lane ldmatrix base offsets (x4: lanes 0-15 rows, lanes 16-31 +16B k-half)
    uint32_t arow = (uint32_t)(wm * 64 + (lane & 15)) * ROWB + ((lane >> 4) * 16);
    uint32_t brow = (uint32_t)(wn * 32 + (lane & 15)) * ROWB + ((lane >> 4) * 16);

    for (int c = 0; c < NK; c++) {
        int st = c % NSTAGE;
        cp_wait1();          // stage c resident (<=1 newer group outstanding)
        __syncthreads();     // also fences stage (c % NSTAGE) reads from last round
        if (c + 2 < NK) load_stage((c + 2) % NSTAGE, (c + 2) * BK);
        cp_commit();

        uint32_t sbase = sb + st * STG_BYTES;
#pragma unroll
        for (int kk = 0; kk < 2; kk++) {
            uint32_t ah[4][4];
#pragma unroll
            for (int mt = 0; mt < 4; mt++)
                ldsm4(ah[mt], sbase + RG_A + arow + mt * (16 * ROWB) + kk * 32);
            uint32_t bh[2][4];
#pragma unroll
            for (int j = 0; j < 2; j++)
                ldsm4(bh[j], sbase + RG_B + brow + j * (16 * ROWB) + kk * 32);
#pragma unroll
            for (int mt = 0; mt < 4; mt++)
#pragma unroll
                for (int j = 0; j < 2; j++)
#pragma unroll
                    for (int s = 0; s < 2; s++)
                        mma_f16(acc[mt][j * 2 + s], ah[mt], bh[j][s], bh[j][s + 2]);
        }
    }
    __syncthreads();
}

// ---------------- GEMM1: h = gelu(gather(x) @ W1 + b1) ----------------
__global__ __launch_bounds__(256, 1) void gemm1_mma(const float* __restrict__ b1) {
    int e = blockIdx.z;
    int len = g_len[e];
    int row0 = blockIdx.y * BM;
    if (row0 >= len) return;
    int col0 = blockIdx.x * BN;

    extern __shared__ __align__(128) char smem_d[];
    uint32_t sb = smem_u32(smem_d);

    float acc[4][4][4];
#pragma unroll
    for (int i = 0; i < 4; i++)
#pragma unroll
        for (int j = 0; j < 4; j++)
#pragma unroll
            for (int k = 0; k < 4; k++) acc[i][j][k] = 0.f;

    gemm_core<true>(e, len, row0, col0, sb, acc);

    int lane = threadIdx.x & 31, wid = threadIdx.x >> 5;
    int wm = wid & 1, wn = wid >> 1;
    const float* bb = b1 + (size_t)e * HID;
#pragma unroll
    for (int mt = 0; mt < 4; mt++) {
        int rA = row0 + wm * 64 + mt * 16 + (lane >> 2);
        int rB = rA + 8;
        bool vA = rA < len, vB = rB < len;
        __half* hA = g_h16 + ((size_t)e * CAPCT + rA) * HID;
        __half* hB = g_h16 + ((size_t)e * CAPCT + rB) * HID;
#pragma unroll
        for (int nt = 0; nt < 4; nt++) {
            int col = col0 + wn * 32 + nt * 8 + (lane & 3) * 2;
            float bv0 = bb[col], bv1 = bb[col + 1];
            if (vA) {
                float x0 = gelu_exact(acc[mt][nt][0] + bv0);
                float x1 = gelu_exact(acc[mt][nt][1] + bv1);
                *(__half2*)(hA + col) = __floats2half2_rn(x0, x1);
            }
            if (vB) {
                float x0 = gelu_exact(acc[mt][nt][2] + bv0);
                float x1 = gelu_exact(acc[mt][nt][3] + bv1);
                *(__half2*)(hB + col) = __floats2half2_rn(x0, x1);
            }
        }
    }
}

// ---------------- GEMM2: out[tok] += gw * (h @ W2 + b2) ----------------
__global__ __launch_bounds__(256, 1) void gemm2_mma(const float* __restrict__ b2,
                                                    float* __restrict__ out) {
    int e = blockIdx.z;
    int len = g_len[e];
    int row0 = blockIdx.y * BM;
    if (row0 >= len) return;
    int col0 = blockIdx.x * BN;

    extern __shared__ __align__(128) char smem_d[];
    uint32_t sb = smem_u32(smem_d);

    float acc[4][4][4];
#pragma unroll
    for (int i = 0; i < 4; i++)
#pragma unroll
        for (int j = 0; j < 4; j++)
#pragma unroll
            for (int k = 0; k < 4; k++) acc[i][j][k] = 0.f;

    gemm_core<false>(e, len, row0, col0, sb, acc);

    int lane = threadIdx.x & 31, wid = threadIdx.x >> 5;
    int wm = wid & 1, wn = wid >> 1;
    const float* bb = b2 + (size_t)e * DIMSZ;
#pragma unroll
    for (int mt = 0; mt < 4; mt++) {
        int rA = row0 + wm * 64 + mt * 16 + (lane >> 2);
        int rB = rA + 8;
        bool vA = rA < len, vB = rB < len;
        int   tokA = vA ? g_tok[e * CAPCT + rA] : 0;
        float gwA  = vA ? g_gw[e * CAPCT + rA]  : 0.f;
        int   tokB = vB ? g_tok[e * CAPCT + rB] : 0;
        float gwB  = vB ? g_gw[e * CAPCT + rB]  : 0.f;
        float* oA = out + (size_t)tokA * DIMSZ;
        float* oB = out + (size_t)tokB * DIMSZ;
#pragma unroll
        for (int nt = 0; nt < 4; nt++) {
            int col = col0 + wn * 32 + nt * 8 + (lane & 3) * 2;
            float bv0 = bb[col], bv1 = bb[col + 1];
            if (vA) {
                atomicAdd(oA + col,     (acc[mt][nt][0] + bv0) * gwA);
                atomicAdd(oA + col + 1, (acc[mt][nt][1] + bv1) * gwA);
            }
            if (vB) {
                atomicAdd(oB + col,     (acc[mt][nt][2] + bv0) * gwB);
                atomicAdd(oB + col + 1, (acc[mt][nt][3] + bv1) * gwB);
            }
        }
    }
}

// ---------------- aux loss ----------------
__global__ void aux_kernel(float* out, int out_size) {
    if ((size_t)out_size <= (size_t)BTOK * DIMSZ) return;
    float proc[NEXP];
    float psum = 0.f;
#pragma unroll
    for (int e = 0; e < NEXP; e++) {
        proc[e] = fminf((float)g_count[e], (float)CAPCT);
        psum += proc[e];
    }
    float inv = 1.f / fmaxf(psum, 1.f);
    float lb = 0.f;
#pragma unroll
    for (int e = 0; e < NEXP; e++)
        lb += (g_usage[e] / (float)BTOK) * (proc[e] * inv);
    lb *= (float)NEXP;
    float zl = g_z2 / (float)BTOK;
    out[(size_t)BTOK * DIMSZ] = 0.01f * lb + 0.01f * zl;
}

// ---------------- launch ----------------
extern "C" void kernel_launch(void* const* d_in, const int* in_sizes, int n_in,
                              void* d_out, int out_size) {
    const float* x  = (const float*)d_in[0];
    const float* rw = (const float*)d_in[1];
    const float* w1 = (const float*)d_in[2];
    const float* b1 = (const float*)d_in[3];
    const float* w2 = (const float*)d_in[4];
    const float* b2 = (const float*)d_in[5];
    float* out = (float*)d_out;

    cudaFuncSetAttribute(gemm1_mma, cudaFuncAttributeMaxDynamicSharedMemorySize, SMEM_G);
    cudaFuncSetAttribute(gemm2_mma, cudaFuncAttributeMaxDynamicSharedMemorySize, SMEM_G);

    cudaMemsetAsync(out, 0, (size_t)BTOK * DIMSZ * sizeof(float), 0);
    init_kernel<<<1, 64>>>();
    conv_x_kernel<<<(BTOK * DIMSZ / 4) / 256, 256>>>(x);
    conv_tr_kernel<<<dim3(HID / 32, DIMSZ / 32, NEXP), 256>>>(w1, 0, DIMSZ, HID);
    conv_tr_kernel<<<dim3(DIMSZ / 32, HID / 32, NEXP), 256>>>(w2, 1, HID, DIMSZ);
    router_kernel<<<BTOK / 32, 256>>>(x, rw);
    select_kernel<<<NEXP, 256>>>();
    build_kernel<<<NSLOT / 256, 256>>>();
    gemm1_mma<<<dim3(HID / BN, CAPCT / BM, NEXP), 256, SMEM_G>>>(b1);
    gemm2_mma<<<dim3(DIMSZ / BN, CAPCT / BM, NEXP), 256, SMEM_G>>>(b2, out);
    aux_kernel<<<1, 1>>>(out, out_size);
}